// round 16
// baseline (speedup 1.0000x reference)
#include <cuda_runtime.h>
#include <cuda_bf16.h>
#include <math.h>

#define Bv   16384
#define Tv   60
#define Hv   128
#define NXv  4
#define NYv  4
#define NYSv 3

typedef unsigned int u32;

// ---- SMEM layout (bytes) ----
#define B_OFF    131072            // A hi[0,64K) lo[64K,128K); B ring 2x32KB
#define BIAS_OFF 196608
#define WX_OFF   198656
#define XS_OFF   206848
#define MB_OFF   208896            // full0,full1,free0,free1 (8B each)
#define SMEM_SZ  208960

// ---- device scratch ----
__device__ char  g_Wslab[(size_t)2 * 16 * 32768];
__device__ float g_bp[2 * 512];
__device__ float g_Wx[512 * 4];
__device__ float g_h1[Bv * Hv];
__device__ float g_c1[Bv * Hv];
__device__ char  g_blob[(size_t)128 * Tv * 65536];     // layer1 h blobs (hi32K+lo32K)
__device__ char  g_mblob[(size_t)128 * Tv * 65536];    // mem0 pre-converted blobs
__device__ char  g_hb2[(size_t)128 * 2 * 65536];       // layer2 h ping-pong
__device__ float g_r2[(size_t)Tv * Bv * Hv];
__device__ float g_wcomb[NYv * Hv];
__device__ float g_bcomb[NYv];

// ---- helpers ----
__device__ __forceinline__ u32 smem_u32(const void* p) {
    u32 a; asm("{ .reg .u64 t; cvta.to.shared.u64 t, %1; cvt.u32.u64 %0, t; }" : "=r"(a) : "l"(p));
    return a;
}
__device__ __forceinline__ void ldsm4(u32* r, u32 a) {
    asm volatile("ldmatrix.sync.aligned.m8n8.x4.shared.b16 {%0,%1,%2,%3}, [%4];"
        : "=r"(r[0]), "=r"(r[1]), "=r"(r[2]), "=r"(r[3]) : "r"(a));
}
__device__ __forceinline__ void mma_bf(float* d, const u32* a, const u32* b) {
    asm volatile("mma.sync.aligned.m16n8k16.row.col.f32.bf16.bf16.f32 "
        "{%0,%1,%2,%3},{%4,%5,%6,%7},{%8,%9},{%0,%1,%2,%3};"
        : "+f"(d[0]), "+f"(d[1]), "+f"(d[2]), "+f"(d[3])
        : "r"(a[0]), "r"(a[1]), "r"(a[2]), "r"(a[3]), "r"(b[0]), "r"(b[1]));
}
__device__ __forceinline__ void cpa16(u32 dst, const void* src) {
    asm volatile("cp.async.cg.shared.global [%0], [%1], 16;" :: "r"(dst), "l"(src));
}
#define CP_COMMIT() asm volatile("cp.async.commit_group;" ::: "memory")
#define CP_WAIT0()  asm volatile("cp.async.wait_group 0;" ::: "memory")
#define BAR1()      asm volatile("bar.sync 1, 256;" ::: "memory")

#define MBAR_INIT(a, c)  asm volatile("mbarrier.init.shared.b64 [%0], %1;" :: "r"(a), "r"(c) : "memory")
#define MBAR_ARRIVE(a)   asm volatile("mbarrier.arrive.shared.b64 _, [%0];" :: "r"(a) : "memory")
#define MBAR_EXPECT(a,b) asm volatile("mbarrier.arrive.expect_tx.shared.b64 _, [%0], %1;" :: "r"(a), "r"(b) : "memory")
#define MBAR_WAIT(a, ph) do { u32 _m=(a), _p=(ph); \
    asm volatile("{\n\t.reg .pred P;\n\tW%=:\n\tmbarrier.try_wait.parity.acquire.cta.shared::cta.b64 P, [%0], %1, 0x989680;\n\t@P bra.uni D%=;\n\tbra.uni W%=;\n\tD%=:\n\t}" \
    :: "r"(_m), "r"(_p) : "memory"); } while(0)
#define MBAR_WAIT_RLX(a, ph) do { u32 _m=(a), _p=(ph); \
    asm volatile("{\n\t.reg .pred P;\n\tW%=:\n\tmbarrier.try_wait.parity.relaxed.cta.shared::cta.b64 P, [%0], %1, 0x989680;\n\t@P bra.uni D%=;\n\tbra.uni W%=;\n\tD%=:\n\t}" \
    :: "r"(_m), "r"(_p) : "memory"); } while(0)
#define CP_BULK(dst, src, mbar) \
    asm volatile("cp.async.bulk.shared::cluster.global.mbarrier::complete_tx::bytes [%0], [%1], %2, [%3];" \
        :: "r"(dst), "l"(src), "r"(32768), "r"(mbar) : "memory")

__device__ __forceinline__ float sigf(float x)   { return __fdividef(1.0f, 1.0f + __expf(-x)); }
__device__ __forceinline__ float tanhf_(float x) { return __fdividef(2.0f, 1.0f + __expf(-2.0f * x)) - 1.0f; }
__device__ __forceinline__ u32 packbf(float a, float b) {
    __nv_bfloat162 t = __floats2bfloat162_rn(a, b);
    return *(u32*)&t;
}

// ---- init: layer1 h0/c0 ----
__global__ void init_kernel(const float* __restrict__ sfc,
                            const float* __restrict__ Ws1, const float* __restrict__ bs1,
                            const float* __restrict__ Ws2, const float* __restrict__ bs2)
{
    int i = blockIdx.x * blockDim.x + threadIdx.x;
    if (i >= Bv * Hv) return;
    int b = i >> 7, j = i & 127;
    float s0 = sfc[b*3+0], s1 = sfc[b*3+1], s2 = sfc[b*3+2];
    g_h1[i] = tanhf(bs1[j] + s0*Ws1[j*3+0] + s1*Ws1[j*3+1] + s2*Ws1[j*3+2]);
    g_c1[i] = tanhf(bs2[j] + s0*Ws2[j*3+0] + s1*Ws2[j*3+1] + s2*Ws2[j*3+2]);
}

// ---- conv_mem0: pre-convert mem0 -> swizzled bf16 hi/lo blobs ----
__global__ void conv_mem0(const float* __restrict__ mem0)
{
    size_t i = (size_t)blockIdx.x * blockDim.x + threadIdx.x;
    if (i >= (size_t)128 * Tv * 128 * 64) return;
    int kp = i & 63;
    int r  = (int)((i >> 6) & 127);
    int t  = (int)((i >> 13) % Tv);
    int cta = (int)(i / ((size_t)Tv * 8192));
    const float* src = mem0 + ((size_t)(cta * 128 + r) * Tv + t) * 128 + kp * 2;
    float2 v = *(const float2*)src;
    __nv_bfloat16 h0 = __float2bfloat16_rn(v.x), h1 = __float2bfloat16_rn(v.y);
    u32 hw = (u32)*(unsigned short*)&h0 | ((u32)*(unsigned short*)&h1 << 16);
    u32 lw = packbf(v.x - __bfloat162float(h0), v.y - __bfloat162float(h1));
    char* dst = g_mblob + ((size_t)cta * Tv + t) * 65536;
    int off = r * 256 + ((kp * 4) ^ ((r & 7) << 4));
    *(u32*)(dst + off) = hw;
    *(u32*)(dst + 32768 + off) = lw;
}

// ---- prep: split+swizzle weight slabs, biases, Wx, folded out projection ----
__global__ void prep_kernel(const float* __restrict__ Wih1, const float* __restrict__ Whh1,
                            const float* __restrict__ bih1, const float* __restrict__ bhh1,
                            const float* __restrict__ Wih2, const float* __restrict__ Whh2,
                            const float* __restrict__ bih2, const float* __restrict__ bhh2,
                            const float* __restrict__ Wlat, const float* __restrict__ blat,
                            const float* __restrict__ Wout, const float* __restrict__ bout)
{
    int idx = blockIdx.x * blockDim.x + threadIdx.x;
    const int NB = 2 * 16 * 128 * 128;
    if (idx < NB) {
        int layer = idx >> 18;
        int rem = idx & 262143;
        int slab = rem >> 14;
        int n = (rem >> 7) & 127, kloc = rem & 127;
        int ci = slab >> 2, sl = slab & 3, term = sl >> 1, kh = sl & 1;
        int k = kh * 128 + kloc;
        int q = (n >> 3) & 3, jj = ((n >> 5) << 3) + (n & 7);
        int g = q * 128 + ci * 32 + jj;
        float w;
        if (layer == 0) w = (k < 128) ? Wih1[g*132 + 4 + k] : Whh1[g*128 + k - 128];
        else            w = (k < 128) ? Wih2[g*128 + k]     : Whh2[g*128 + k - 128];
        __nv_bfloat16 hi = __float2bfloat16_rn(w);
        float lo = w - __bfloat162float(hi);
        __nv_bfloat16 v = term ? __float2bfloat16_rn(lo) : hi;
        size_t base = (size_t)(layer * 16 + slab) << 15;
        *(__nv_bfloat16*)(g_Wslab + base + n*256 + ((2*kloc) ^ ((n & 7) << 4))) = v;
        return;
    }
    int i2 = idx - NB;
    if (i2 < 2048) {
        int m = i2 >> 2, f = i2 & 3;
        int ci = m >> 7, n = m & 127;
        int q = (n >> 3) & 3, jj = ((n >> 5) << 3) + (n & 7);
        int g = q * 128 + ci * 32 + jj;
        g_Wx[i2] = Wih1[g * 132 + f];
        return;
    }
    int i3 = i2 - 2048;
    if (i3 < 1024) {
        int layer = i3 >> 9, m = i3 & 511;
        int ci = m >> 7, n = m & 127;
        int q = (n >> 3) & 3, jj = ((n >> 5) << 3) + (n & 7);
        int g = q * 128 + ci * 32 + jj;
        g_bp[i3] = layer ? (bih2[g] + bhh2[g]) : (bih1[g] + bhh1[g]);
        return;
    }
    int i4 = i3 - 1024;
    if (i4 < 512) {
        int y = i4 >> 7, j = i4 & 127;
        float acc = 0.0f;
        for (int k = 0; k < Hv; k++) acc += Wout[y*Hv+k] * Wlat[k*Hv+j];
        g_wcomb[i4] = acc;
        if (i4 < NYv) {
            float bb = bout[i4];
            for (int k = 0; k < Hv; k++) bb += Wout[i4*Hv+k] * blat[k];
            g_bcomb[i4] = bb;
        }
    }
}

// ---- stage fp32 -> swizzled bf16 hi/lo into A half (t==0 only) ----
__device__ __forceinline__ void conv_split(char* sm, const float* src, int srcStride, int koff, int tid)
{
    for (int idx = tid; idx < 8192; idx += 256) {
        int r = idx >> 6, kp = idx & 63;
        float2 v = *(const float2*)(src + (size_t)r * srcStride + kp * 2);
        __nv_bfloat16 h0 = __float2bfloat16_rn(v.x), h1 = __float2bfloat16_rn(v.y);
        u32 hw = (u32)*(unsigned short*)&h0 | ((u32)*(unsigned short*)&h1 << 16);
        u32 lw = packbf(v.x - __bfloat162float(h0), v.y - __bfloat162float(h1));
        int byte = r * 512 + (((koff + kp * 2) * 2) ^ ((r & 7) << 4));
        *(u32*)(sm + byte) = hw;
        *(u32*)(sm + 65536 + byte) = lw;
    }
}
// ---- LDG/STS copy of pre-swizzled blob into A at dstAdd ----
__device__ __forceinline__ void copy_blob(char* sm, const char* src, int dstAdd, int tid)
{
    for (int i = tid; i < 2048; i += 256) {
        int r = i >> 4, cb = (i & 15) << 4;
        *(uint4*)(sm + r*512 + dstAdd + cb) = *(const uint4*)(src + r*256 + cb);
        *(uint4*)(sm + 65536 + r*512 + dstAdd + cb) = *(const uint4*)(src + 32768 + r*256 + cb);
    }
}
// ---- cp.async copy of blob into A input half (source from a prior kernel) ----
__device__ __forceinline__ void stage_cp(u32 sbA, const char* src, int tid)
{
    for (int i = tid; i < 4096; i += 256) {
        int half = i >> 11, r = (i >> 4) & 127, c = (i & 15) << 4;
        cpa16(sbA + half*65536 + r*512 + c, src + half*32768 + r*256 + c);
    }
}

// ---- persistent HMMA 2-layer LSTM, producer-warp weight streaming ----
__global__ __launch_bounds__(288, 1) void rnn_mma(
    const float* __restrict__ inputs_main,
    const float* __restrict__ hx2, const float* __restrict__ cx2)
{
    extern __shared__ char sm[];
    float* bias_s = (float*)(sm + BIAS_OFF);
    float* wx_s   = (float*)(sm + WX_OFF);
    float* xs_s   = (float*)(sm + XS_OFF);
    const u32 sb = smem_u32(sm);
    const u32 mbF = sb + MB_OFF;        // full0, full1
    const u32 mbE = sb + MB_OFF + 16;   // free0, free1
    const int tid = threadIdx.x;
    const int w = tid >> 5, l = tid & 31;
    const int bB = blockIdx.x * 128;
    const size_t SLAB = (size_t)Bv * Hv;

    if (tid == 0) {
        MBAR_INIT(mbF + 0, 1); MBAR_INIT(mbF + 8, 1);
        MBAR_INIT(mbE + 0, 8); MBAR_INIT(mbE + 8, 8);
    }
    __syncthreads();

    if (w == 8) {
        // ================= producer warp =================
        if (l == 0) {
            int sn = 0;
            for (int g = 0; g < 2 * Tv; ++g) {
                const char* wb = g_Wslab + ((size_t)(g < Tv ? 0 : 1) << 19);
                for (int s = 0; s < 16; ++s, ++sn) {
                    int slot = sn & 1, ph = (sn >> 1) & 1;
                    MBAR_WAIT_RLX(mbE + slot*8, ph);
                    MBAR_EXPECT(mbF + slot*8, 32768);
                    CP_BULK(sb + B_OFF + (u32)(slot << 15), wb + ((size_t)s << 15), mbF + slot*8);
                }
            }
        }
        return;
    }

    // ================= compute warps (0-7) =================
    if (l == 0) { MBAR_ARRIVE(mbE + 0); MBAR_ARRIVE(mbE + 8); }   // pre-release ring
    const int wm = w >> 2, wn = w & 3;
    const int lr = l >> 2, cc0 = 2 * (l & 3);

    const int rA = wm * 64 + (l & 15);
    const u32 aBase = sb + rA * 512;
    const u32 kLaneA = (u32)((l >> 4) << 4);
    const u32 sxA = (u32)((rA & 7) << 4);
    const int nB = wn * 32 + ((l >> 4) << 3) + (l & 7);
    const u32 kLaneB = (u32)(((l >> 3) & 1) << 4);
    const u32 sxB = (u32)((l & 7) << 4);

    for (int i = tid; i < 2048; i += 256) wx_s[i] = g_Wx[i];

    float c_reg[64];
    float acc[4][4][4];
    int gstep = 0;

    for (int layer = 0; layer < 2; ++layer) {
        BAR1();
        for (int i = tid; i < 512; i += 256) bias_s[i] = g_bp[layer * 512 + i];
        {
            const float* c0 = layer ? cx2 : g_c1;
#pragma unroll
            for (int mi = 0; mi < 4; mi++)
#pragma unroll
            for (int rr = 0; rr < 2; rr++) {
                int row = wm*64 + mi*16 + lr + rr*8;
#pragma unroll
                for (int c4 = 0; c4 < 4; c4++) {
                    float2 v = *(const float2*)&c0[(size_t)(bB + row) * 128 + c4*32 + wn*8 + cc0];
                    c_reg[(mi*2+rr)*8 + c4*2]     = v.x;
                    c_reg[(mi*2+rr)*8 + c4*2 + 1] = v.y;
                }
            }
        }

        for (int t = 0; t < Tv; ++t) {
            const int ta = layer ? t : (Tv - 1 - t);
            BAR1();   // all warps done with previous A; epilogue STGs ordered

            if (layer == 0) {
                stage_cp(sb, g_mblob + ((size_t)blockIdx.x * Tv + t) * 65536, tid);
                CP_COMMIT();
                if (t == 0) conv_split(sm, g_h1 + (size_t)bB * 128, 128, 128, tid);
                else copy_blob(sm, g_blob + ((size_t)blockIdx.x * Tv + (ta + 1)) * 65536, 256, tid);
                if (tid < 128)
                    *(float4*)&xs_s[tid*4] = *(const float4*)(inputs_main + ((size_t)(bB + tid) * Tv + ta) * 4);
                CP_WAIT0();
            } else {
                copy_blob(sm, g_blob + ((size_t)blockIdx.x * Tv + t) * 65536, 0, tid);
                if (t == 0) conv_split(sm, hx2 + (size_t)bB * 128, 128, 128, tid);
                else copy_blob(sm, g_hb2 + ((size_t)(blockIdx.x * 2 + ((t - 1) & 1))) * 65536, 256, tid);
            }
            BAR1();   // A ready

            for (int s = 0; s < 16; ++s) {
                const int sn = gstep * 16 + s;
                const int slot = sn & 1, ph = (sn >> 1) & 1;
                MBAR_WAIT(mbF + slot*8, ph);

                if ((s & 3) == 0) {
                    int bb0 = (s >> 2) * 128 + wn * 32 + cc0;
#pragma unroll
                    for (int ni = 0; ni < 4; ni++) {
                        float v0 = bias_s[bb0 + ni*8], v1 = bias_s[bb0 + ni*8 + 1];
#pragma unroll
                        for (int mi = 0; mi < 4; mi++) {
                            acc[mi][ni][0] = v0; acc[mi][ni][1] = v1;
                            acc[mi][ni][2] = v0; acc[mi][ni][3] = v1;
                        }
                    }
                }

                const u32 bbase = sb + B_OFF + ((u32)slot << 15) + nB * 256;
                const u32 kb0 = (u32)(s & 1) << 8;
                const bool hi_term = (s & 2) == 0;
#pragma unroll
                for (int kk = 0; kk < 8; kk++) {
                    u32 aoff = (((kb0 + kk*32) | kLaneA) ^ sxA);
                    u32 boff = ((((u32)kk << 5) | kLaneB) ^ sxB);
                    u32 b[8];
                    ldsm4(b, bbase + boff);
                    ldsm4(b + 4, bbase + 4096 + boff);
                    u32 a[16];
                    ldsm4(a,      aBase + aoff);
                    ldsm4(a + 4,  aBase + 8192 + aoff);
                    ldsm4(a + 8,  aBase + 16384 + aoff);
                    ldsm4(a + 12, aBase + 24576 + aoff);
#pragma unroll
                    for (int mi = 0; mi < 4; mi++)
#pragma unroll
                    for (int ni = 0; ni < 4; ni++)
                        mma_bf(acc[mi][ni], a + 4*mi, b + 2*ni);
                    if (hi_term) {
                        u32 al[16];
                        ldsm4(al,      aBase + 65536 + aoff);
                        ldsm4(al + 4,  aBase + 73728 + aoff);
                        ldsm4(al + 8,  aBase + 81920 + aoff);
                        ldsm4(al + 12, aBase + 90112 + aoff);
#pragma unroll
                        for (int mi = 0; mi < 4; mi++)
#pragma unroll
                        for (int ni = 0; ni < 4; ni++)
                            mma_bf(acc[mi][ni], al + 4*mi, b + 2*ni);
                    }
                }
                if (l == 0) MBAR_ARRIVE(mbE + slot*8);   // after mma issues: smem reads done

                if ((s & 3) == 3) {   // ---- epilogue for ci ----
                    int ci = s >> 2;
                    int j0c = ci*32 + wn*8 + cc0;
                    float4 wq[4][2];
                    if (layer == 0) {
#pragma unroll
                        for (int q = 0; q < 4; q++) {
                            int ng = ci*128 + wn*32 + q*8 + cc0;
                            wq[q][0] = *(const float4*)&wx_s[ng * 4];
                            wq[q][1] = *(const float4*)&wx_s[ng * 4 + 4];
                        }
                    }
#pragma unroll
                    for (int mi = 0; mi < 4; mi++)
#pragma unroll
                    for (int rr = 0; rr < 2; rr++) {
                        int row = wm*64 + mi*16 + lr + rr*8;
                        float4 xr = make_float4(0.f, 0.f, 0.f, 0.f);
                        if (layer == 0) xr = *(const float4*)&xs_s[row * 4];
                        float hh[2];
#pragma unroll
                        for (int u = 0; u < 2; u++) {
                            float zi = acc[mi][0][rr*2+u], zf = acc[mi][1][rr*2+u];
                            float zg = acc[mi][2][rr*2+u], zo = acc[mi][3][rr*2+u];
                            if (layer == 0) {
                                zi += wq[0][u].x*xr.x + wq[0][u].y*xr.y + wq[0][u].z*xr.z + wq[0][u].w*xr.w;
                                zf += wq[1][u].x*xr.x + wq[1][u].y*xr.y + wq[1][u].z*xr.z + wq[1][u].w*xr.w;
                                zg += wq[2][u].x*xr.x + wq[2][u].y*xr.y + wq[2][u].z*xr.z + wq[2][u].w*xr.w;
                                zo += wq[3][u].x*xr.x + wq[3][u].y*xr.y + wq[3][u].z*xr.z + wq[3][u].w*xr.w;
                            }
                            int cidx = (mi*2+rr)*8 + ci*2 + u;
                            float cn = sigf(zf) * c_reg[cidx] + sigf(zi) * tanhf_(zg);
                            hh[u] = sigf(zo) * tanhf_(cn);
                            c_reg[cidx] = cn;
                        }
                        __nv_bfloat16 q0 = __float2bfloat16_rn(hh[0]), q1 = __float2bfloat16_rn(hh[1]);
                        u32 hw = (u32)*(unsigned short*)&q0 | ((u32)*(unsigned short*)&q1 << 16);
                        u32 lw = packbf(hh[0] - __bfloat162float(q0), hh[1] - __bfloat162float(q1));
                        int bo = row * 256 + ((2 * j0c) ^ ((row & 7) << 4));
                        if (layer == 0) {
                            char* bb = g_blob + ((size_t)blockIdx.x * Tv + ta) * 65536;
                            *(u32*)(bb + bo) = hw;
                            *(u32*)(bb + 32768 + bo) = lw;
                        } else {
                            char* bb = g_hb2 + ((size_t)(blockIdx.x * 2 + (t & 1))) * 65536;
                            *(u32*)(bb + bo) = hw;
                            *(u32*)(bb + 32768 + bo) = lw;
                            *(float2*)(g_r2 + (size_t)t * SLAB + (size_t)(bB + row) * 128 + j0c) =
                                make_float2(hh[0], hh[1]);
                        }
                    }
                }
            }
            gstep++;
        }
    }
}

// ---- out = r2 @ Wcomb^T + bcomb ----
__global__ void out_kernel(const float* __restrict__ r2, float* __restrict__ out)
{
    __shared__ float sw[NYv * 129];
    __shared__ float sr[32][129];
    int tid = threadIdx.x;
    for (int i = tid; i < NYv * Hv; i += 128) {
        int y = i >> 7, k = i & 127;
        sw[y * 129 + k] = g_wcomb[i];
    }
    size_t base = (size_t)blockIdx.x * 32 * Hv;
    for (int i = tid; i < 32 * Hv; i += 128) {
        int rr = i >> 7, kk = i & 127;
        sr[rr][kk] = r2[base + i];
    }
    __syncthreads();
    int r = tid >> 2, y = tid & 3;
    int n = blockIdx.x * 32 + r;
    int t = n >> 14;
    int b = n & (Bv - 1);
    float acc = g_bcomb[y];
#pragma unroll 4
    for (int k = 0; k < Hv; k++) acc += sw[y * 129 + k] * sr[r][k];
    out[((size_t)b * Tv + t) * NYv + y] = acc;
}

__global__ void sfc_kernel(const float* __restrict__ Wsfc, const float* __restrict__ bsfc,
                           const float* __restrict__ hN, float* __restrict__ osfc)
{
    int i = blockIdx.x * blockDim.x + threadIdx.x;
    if (i >= Bv * NYSv) return;
    int b = i / 3, y = i - b * 3;
    const float* h = hN + (size_t)b * Hv;
    float acc = bsfc[y];
#pragma unroll 4
    for (int k = 0; k < Hv; k++) acc += Wsfc[y * Hv + k] * h[k];
    osfc[i] = acc;
}

// ---- launch ----
extern "C" void kernel_launch(void* const* d_in, const int* in_sizes, int n_in,
                              void* d_out, int out_size)
{
    const float* inputs_main = (const float*)d_in[0];
    const float* inputs_sfc  = (const float*)d_in[1];
    const float* mem0        = (const float*)d_in[2];
    const float* hx2         = (const float*)d_in[3];
    const float* cx2         = (const float*)d_in[4];
    const float* Ws1  = (const float*)d_in[5];
    const float* bs1  = (const float*)d_in[6];
    const float* Ws2  = (const float*)d_in[7];
    const float* bs2  = (const float*)d_in[8];
    const float* Wih1 = (const float*)d_in[9];
    const float* Whh1 = (const float*)d_in[10];
    const float* bih1 = (const float*)d_in[11];
    const float* bhh1 = (const float*)d_in[12];
    const float* Wih2 = (const float*)d_in[13];
    const float* Whh2 = (const float*)d_in[14];
    const float* bih2 = (const float*)d_in[15];
    const float* bhh2 = (const float*)d_in[16];
    const float* Wlat = (const float*)d_in[17];
    const float* blat = (const float*)d_in[18];
    const float* Wout = (const float*)d_in[19];
    const float* bout = (const float*)d_in[20];
    const float* Wsfc = (const float*)d_in[21];
    const float* bsfc = (const float*)d_in[22];
    float* out = (float*)d_out;

    float* r2;
    cudaGetSymbolAddress((void**)&r2, g_r2);

    init_kernel<<<(Bv * Hv + 255) / 256, 256>>>(inputs_sfc, Ws1, bs1, Ws2, bs2);

    const size_t CONV_N = (size_t)128 * Tv * 128 * 64;
    conv_mem0<<<(int)((CONV_N + 255) / 256), 256>>>(mem0);

    const int PREP_N = 2*16*128*128 + 2048 + 1024 + 512;
    prep_kernel<<<(PREP_N + 255) / 256, 256>>>(Wih1, Whh1, bih1, bhh1,
                                               Wih2, Whh2, bih2, bhh2,
                                               Wlat, blat, Wout, bout);

    cudaFuncSetAttribute(rnn_mma, cudaFuncAttributeMaxDynamicSharedMemorySize, SMEM_SZ);
    rnn_mma<<<128, 288, SMEM_SZ>>>(inputs_main, hx2, cx2);

    out_kernel<<<(Bv * Tv) / 32, 128>>>(r2, out);
    sfc_kernel<<<(Bv * NYSv + 255) / 256, 256>>>(Wsfc, bsfc,
                                                 r2 + (size_t)(Tv - 1) * Bv * Hv,
                                                 out + (size_t)Bv * Tv * NYv);
}

// round 17
// speedup vs baseline: 1.1052x; 1.1052x over previous
#include <cuda_runtime.h>
#include <cuda_bf16.h>
#include <math.h>

#define Bv   16384
#define Tv   60
#define Hv   128
#define NXv  4
#define NYv  4
#define NYSv 3

typedef unsigned int u32;

// ---- SMEM layout (bytes): A hi[0,64K) lo[64K,128K); B ring 2x32KB; bias; wx; xs
#define B_OFF    131072
#define BIAS_OFF 196608
#define WX_OFF   198656
#define XS_OFF   206848
#define SMEM_SZ  208896

// ---- device scratch ----
__device__ char  g_Wslab[(size_t)2 * 16 * 32768];      // [layer][ci*4+kq]: whi 16K + wlo 16K
__device__ float g_bp[2 * 512];
__device__ float g_Wx[512 * 4];
__device__ float g_h1[Bv * Hv];
__device__ float g_c1[Bv * Hv];
__device__ char  g_blob[(size_t)128 * Tv * 65536];     // layer1 h blobs (hi32K+lo32K)
__device__ char  g_mblob[(size_t)128 * Tv * 65536];    // mem0 pre-converted blobs
__device__ char  g_hb2[(size_t)128 * 2 * 65536];       // layer2 h ping-pong
__device__ float g_r2[(size_t)Tv * Bv * Hv];
__device__ float g_wcomb[NYv * Hv];
__device__ float g_bcomb[NYv];

// ---- helpers ----
__device__ __forceinline__ u32 smem_u32(const void* p) {
    u32 a; asm("{ .reg .u64 t; cvta.to.shared.u64 t, %1; cvt.u32.u64 %0, t; }" : "=r"(a) : "l"(p));
    return a;
}
__device__ __forceinline__ void ldsm4(u32* r, u32 a) {
    asm volatile("ldmatrix.sync.aligned.m8n8.x4.shared.b16 {%0,%1,%2,%3}, [%4];"
        : "=r"(r[0]), "=r"(r[1]), "=r"(r[2]), "=r"(r[3]) : "r"(a));
}
__device__ __forceinline__ void mma_bf(float* d, const u32* a, const u32* b) {
    asm volatile("mma.sync.aligned.m16n8k16.row.col.f32.bf16.bf16.f32 "
        "{%0,%1,%2,%3},{%4,%5,%6,%7},{%8,%9},{%0,%1,%2,%3};"
        : "+f"(d[0]), "+f"(d[1]), "+f"(d[2]), "+f"(d[3])
        : "r"(a[0]), "r"(a[1]), "r"(a[2]), "r"(a[3]), "r"(b[0]), "r"(b[1]));
}
__device__ __forceinline__ void cpa16(u32 dst, const void* src) {
    asm volatile("cp.async.cg.shared.global [%0], [%1], 16;" :: "r"(dst), "l"(src));
}
#define CP_COMMIT() asm volatile("cp.async.commit_group;" ::: "memory")

__device__ __forceinline__ float sigf(float x)   { return __fdividef(1.0f, 1.0f + __expf(-x)); }
__device__ __forceinline__ float tanhf_(float x) { return __fdividef(2.0f, 1.0f + __expf(-2.0f * x)) - 1.0f; }
__device__ __forceinline__ u32 packbf(float a, float b) {
    __nv_bfloat162 t = __floats2bfloat162_rn(a, b);
    return *(u32*)&t;
}

// ---- init: layer1 h0/c0 ----
__global__ void init_kernel(const float* __restrict__ sfc,
                            const float* __restrict__ Ws1, const float* __restrict__ bs1,
                            const float* __restrict__ Ws2, const float* __restrict__ bs2)
{
    int i = blockIdx.x * blockDim.x + threadIdx.x;
    if (i >= Bv * Hv) return;
    int b = i >> 7, j = i & 127;
    float s0 = sfc[b*3+0], s1 = sfc[b*3+1], s2 = sfc[b*3+2];
    g_h1[i] = tanhf(bs1[j] + s0*Ws1[j*3+0] + s1*Ws1[j*3+1] + s2*Ws1[j*3+2]);
    g_c1[i] = tanhf(bs2[j] + s0*Ws2[j*3+0] + s1*Ws2[j*3+1] + s2*Ws2[j*3+2]);
}

// ---- conv_mem0: pre-convert mem0 -> swizzled bf16 hi/lo blobs (256B rows) ----
__global__ void conv_mem0(const float* __restrict__ mem0)
{
    size_t i = (size_t)blockIdx.x * blockDim.x + threadIdx.x;
    if (i >= (size_t)128 * Tv * 128 * 64) return;
    int kp = i & 63;
    int r  = (int)((i >> 6) & 127);
    int t  = (int)((i >> 13) % Tv);
    int cta = (int)(i / ((size_t)Tv * 8192));
    const float* src = mem0 + ((size_t)(cta * 128 + r) * Tv + t) * 128 + kp * 2;
    float2 v = *(const float2*)src;
    __nv_bfloat16 h0 = __float2bfloat16_rn(v.x), h1 = __float2bfloat16_rn(v.y);
    u32 hw = (u32)*(unsigned short*)&h0 | ((u32)*(unsigned short*)&h1 << 16);
    u32 lw = packbf(v.x - __bfloat162float(h0), v.y - __bfloat162float(h1));
    char* dst = g_mblob + ((size_t)cta * Tv + t) * 65536;
    int off = r * 256 + ((kp * 4) ^ ((r & 7) << 4));
    *(u32*)(dst + off) = hw;
    *(u32*)(dst + 32768 + off) = lw;
}

// ---- prep: interleaved hi/lo weight slabs, biases, Wx, folded out projection ----
// slab s = ci*4+kq: [whi 128n x 64k][wlo 128n x 64k], 128B swizzled rows.
// col permutation: q=(n>>3)&3, jj=((n>>5)<<3)+(n&7), g=q*128+ci*32+jj
__global__ void prep_kernel(const float* __restrict__ Wih1, const float* __restrict__ Whh1,
                            const float* __restrict__ bih1, const float* __restrict__ bhh1,
                            const float* __restrict__ Wih2, const float* __restrict__ Whh2,
                            const float* __restrict__ bih2, const float* __restrict__ bhh2,
                            const float* __restrict__ Wlat, const float* __restrict__ blat,
                            const float* __restrict__ Wout, const float* __restrict__ bout)
{
    int idx = blockIdx.x * blockDim.x + threadIdx.x;
    const int NB = 2 * 16 * 2 * 128 * 64;   // 524288
    if (idx < NB) {
        int layer = idx >> 18;
        int rem = idx & 262143;
        int slab = rem >> 14;                 // ci*4 + kq
        int term = (rem >> 13) & 1;           // 0=hi 1=lo
        int n = (rem >> 6) & 127, kloc = rem & 63;
        int ci = slab >> 2, kq = slab & 3;
        int k = kq * 64 + kloc;
        int q = (n >> 3) & 3, jj = ((n >> 5) << 3) + (n & 7);
        int g = q * 128 + ci * 32 + jj;
        float w;
        if (layer == 0) w = (k < 128) ? Wih1[g*132 + 4 + k] : Whh1[g*128 + k - 128];
        else            w = (k < 128) ? Wih2[g*128 + k]     : Whh2[g*128 + k - 128];
        __nv_bfloat16 hi = __float2bfloat16_rn(w);
        float lo = w - __bfloat162float(hi);
        __nv_bfloat16 v = term ? __float2bfloat16_rn(lo) : hi;
        size_t base = ((size_t)(layer * 16 + slab) << 15) + term * 16384;
        *(__nv_bfloat16*)(g_Wslab + base + n*128 + ((2*kloc) ^ ((n & 7) << 4))) = v;
        return;
    }
    int i2 = idx - NB;
    if (i2 < 2048) {
        int m = i2 >> 2, f = i2 & 3;
        int ci = m >> 7, n = m & 127;
        int q = (n >> 3) & 3, jj = ((n >> 5) << 3) + (n & 7);
        int g = q * 128 + ci * 32 + jj;
        g_Wx[i2] = Wih1[g * 132 + f];
        return;
    }
    int i3 = i2 - 2048;
    if (i3 < 1024) {
        int layer = i3 >> 9, m = i3 & 511;
        int ci = m >> 7, n = m & 127;
        int q = (n >> 3) & 3, jj = ((n >> 5) << 3) + (n & 7);
        int g = q * 128 + ci * 32 + jj;
        g_bp[i3] = layer ? (bih2[g] + bhh2[g]) : (bih1[g] + bhh1[g]);
        return;
    }
    int i4 = i3 - 1024;
    if (i4 < 512) {
        int y = i4 >> 7, j = i4 & 127;
        float acc = 0.0f;
        for (int k = 0; k < Hv; k++) acc += Wout[y*Hv+k] * Wlat[k*Hv+j];
        g_wcomb[i4] = acc;
        if (i4 < NYv) {
            float bb = bout[i4];
            for (int k = 0; k < Hv; k++) bb += Wout[i4*Hv+k] * blat[k];
            g_bcomb[i4] = bb;
        }
    }
}

// ---- stage fp32 -> swizzled bf16 hi/lo into A half (t==0 only) ----
__device__ __forceinline__ void conv_split(char* sm, const float* src, int srcStride, int koff, int tid)
{
    for (int idx = tid; idx < 8192; idx += 256) {
        int r = idx >> 6, kp = idx & 63;
        float2 v = *(const float2*)(src + (size_t)r * srcStride + kp * 2);
        __nv_bfloat16 h0 = __float2bfloat16_rn(v.x), h1 = __float2bfloat16_rn(v.y);
        u32 hw = (u32)*(unsigned short*)&h0 | ((u32)*(unsigned short*)&h1 << 16);
        u32 lw = packbf(v.x - __bfloat162float(h0), v.y - __bfloat162float(h1));
        int byte = r * 512 + (((koff + kp * 2) * 2) ^ ((r & 7) << 4));
        *(u32*)(sm + byte) = hw;
        *(u32*)(sm + 65536 + byte) = lw;
    }
}
// ---- LDG/STS copy of pre-swizzled blob (256B rows) into A at dstAdd ----
__device__ __forceinline__ void copy_blob(char* sm, const char* src, int dstAdd, int tid)
{
    for (int i = tid; i < 2048; i += 256) {
        int r = i >> 4, cb = (i & 15) << 4;
        *(uint4*)(sm + r*512 + dstAdd + cb) = *(const uint4*)(src + r*256 + cb);
        *(uint4*)(sm + 65536 + r*512 + dstAdd + cb) = *(const uint4*)(src + 32768 + r*256 + cb);
    }
}
// ---- cp.async copy of blob into A input half ----
__device__ __forceinline__ void stage_cp(u32 sbA, const char* src, int tid)
{
    for (int i = tid; i < 4096; i += 256) {
        int half = i >> 11, r = (i >> 4) & 127, c = (i & 15) << 4;
        cpa16(sbA + half*65536 + r*512 + c, src + half*32768 + r*256 + c);
    }
}
// ---- cp.async 32KB weight slab ----
__device__ __forceinline__ void cp_slab(u32 dst, const char* src, int tid)
{
#pragma unroll
    for (int i = 0; i < 8; i++) cpa16(dst + tid*16 + i*4096, src + tid*16 + i*4096);
}

// ---- persistent HMMA 2-layer LSTM, interleaved hi/lo slabs ----
__global__ __launch_bounds__(256, 1) void rnn_mma(
    const float* __restrict__ inputs_main,
    const float* __restrict__ hx2, const float* __restrict__ cx2)
{
    extern __shared__ char sm[];
    float* bias_s = (float*)(sm + BIAS_OFF);
    float* wx_s   = (float*)(sm + WX_OFF);
    float* xs_s   = (float*)(sm + XS_OFF);
    const u32 sb = smem_u32(sm);
    const int tid = threadIdx.x;
    const int w = tid >> 5, l = tid & 31;
    const int wm = w >> 2, wn = w & 3;
    const int lr = l >> 2, cc0 = 2 * (l & 3);
    const int bB = blockIdx.x * 128;
    const size_t SLAB = (size_t)Bv * Hv;

    const int rA = wm * 64 + (l & 15);
    const u32 aBase = sb + rA * 512;
    const u32 kLaneA = (u32)((l >> 4) << 4);
    const u32 sxA = (u32)((rA & 7) << 4);
    const int nB = wn * 32 + ((l >> 4) << 3) + (l & 7);
    const u32 kLaneB = (u32)(((l >> 3) & 1) << 4);
    const u32 sxB = (u32)((l & 7) << 4);

    for (int i = tid; i < 2048; i += 256) wx_s[i] = g_Wx[i];

    float c_reg[64];
    float acc[4][4][4];

    for (int layer = 0; layer < 2; ++layer) {
        __syncthreads();
        for (int i = tid; i < 512; i += 256) bias_s[i] = g_bp[layer * 512 + i];
        {
            const float* c0 = layer ? cx2 : g_c1;
#pragma unroll
            for (int mi = 0; mi < 4; mi++)
#pragma unroll
            for (int rr = 0; rr < 2; rr++) {
                int row = wm*64 + mi*16 + lr + rr*8;
#pragma unroll
                for (int c4 = 0; c4 < 4; c4++) {
                    float2 v = *(const float2*)&c0[(size_t)(bB + row) * 128 + c4*32 + wn*8 + cc0];
                    c_reg[(mi*2+rr)*8 + c4*2]     = v.x;
                    c_reg[(mi*2+rr)*8 + c4*2 + 1] = v.y;
                }
            }
        }
        const char* wbase = g_Wslab + ((size_t)layer << 19);

        for (int t = 0; t < Tv; ++t) {
            const int ta = layer ? t : (Tv - 1 - t);
            __syncthreads();   // prev step fully done; A/B safe to overwrite

            // ---- stage A (+ commit order: [A][s0][s1] for layer0, [s0][s1] else) ----
            if (layer == 0) {
                stage_cp(sb, g_mblob + ((size_t)blockIdx.x * Tv + t) * 65536, tid);
                CP_COMMIT();
            }
            cp_slab(sb + B_OFF, wbase, tid); CP_COMMIT();
            cp_slab(sb + B_OFF + 32768, wbase + 32768, tid); CP_COMMIT();

            if (layer == 0) {
                if (t == 0) conv_split(sm, g_h1 + (size_t)bB * 128, 128, 128, tid);
                else copy_blob(sm, g_blob + ((size_t)blockIdx.x * Tv + (ta + 1)) * 65536, 256, tid);
                if (tid < 128)
                    *(float4*)&xs_s[tid*4] = *(const float4*)(inputs_main + ((size_t)(bB + tid) * Tv + ta) * 4);
            } else {
                copy_blob(sm, g_blob + ((size_t)blockIdx.x * Tv + t) * 65536, 0, tid);
                if (t == 0) conv_split(sm, hx2 + (size_t)bB * 128, 128, 128, tid);
                else copy_blob(sm, g_hb2 + ((size_t)(blockIdx.x * 2 + ((t - 1) & 1))) * 65536, 256, tid);
            }

            for (int s = 0; s < 16; ++s) {
                if (s < 15) asm volatile("cp.async.wait_group 1;" ::: "memory");
                else        asm volatile("cp.async.wait_group 0;" ::: "memory");
                __syncthreads();

                const int ci = s >> 2, kq = s & 3;
                if ((s & 3) == 0) {
                    int bb0 = ci * 128 + wn * 32 + cc0;
#pragma unroll
                    for (int ni = 0; ni < 4; ni++) {
                        float v0 = bias_s[bb0 + ni*8], v1 = bias_s[bb0 + ni*8 + 1];
#pragma unroll
                        for (int mi = 0; mi < 4; mi++) {
                            acc[mi][ni][0] = v0; acc[mi][ni][1] = v1;
                            acc[mi][ni][2] = v0; acc[mi][ni][3] = v1;
                        }
                    }
                }

                const u32 bslab = sb + B_OFF + ((u32)(s & 1) << 15) + nB * 128;
                const u32 kbA = (u32)(kq << 7);
#pragma unroll
                for (int kk = 0; kk < 4; kk++) {
                    u32 aoff = (((kbA + kk*32) | kLaneA) ^ sxA);
                    u32 boff = ((((u32)kk << 5) | kLaneB) ^ sxB);
                    u32 bh[8];
                    ldsm4(bh, bslab + boff);
                    ldsm4(bh + 4, bslab + 2048 + boff);
                    u32 a[16];
                    ldsm4(a,      aBase + aoff);
                    ldsm4(a + 4,  aBase + 8192 + aoff);
                    ldsm4(a + 8,  aBase + 16384 + aoff);
                    ldsm4(a + 12, aBase + 24576 + aoff);
#pragma unroll
                    for (int mi = 0; mi < 4; mi++)
#pragma unroll
                    for (int ni = 0; ni < 4; ni++)
                        mma_bf(acc[mi][ni], a + 4*mi, bh + 2*ni);
                    u32 al[16];
                    ldsm4(al,      aBase + 65536 + aoff);
                    ldsm4(al + 4,  aBase + 73728 + aoff);
                    ldsm4(al + 8,  aBase + 81920 + aoff);
                    ldsm4(al + 12, aBase + 90112 + aoff);
#pragma unroll
                    for (int mi = 0; mi < 4; mi++)
#pragma unroll
                    for (int ni = 0; ni < 4; ni++)
                        mma_bf(acc[mi][ni], al + 4*mi, bh + 2*ni);
                    u32 bl[8];
                    ldsm4(bl, bslab + 16384 + boff);
                    ldsm4(bl + 4, bslab + 16384 + 2048 + boff);
#pragma unroll
                    for (int mi = 0; mi < 4; mi++)
#pragma unroll
                    for (int ni = 0; ni < 4; ni++)
                        mma_bf(acc[mi][ni], a + 4*mi, bl + 2*ni);
                }

                if ((s & 3) == 3) {   // ---- epilogue for ci ----
                    int j0c = ci*32 + wn*8 + cc0;
                    float4 wq[4][2];
                    if (layer == 0) {
#pragma unroll
                        for (int q = 0; q < 4; q++) {
                            int ng = ci*128 + wn*32 + q*8 + cc0;
                            wq[q][0] = *(const float4*)&wx_s[ng * 4];
                            wq[q][1] = *(const float4*)&wx_s[ng * 4 + 4];
                        }
                    }
#pragma unroll
                    for (int mi = 0; mi < 4; mi++)
#pragma unroll
                    for (int rr = 0; rr < 2; rr++) {
                        int row = wm*64 + mi*16 + lr + rr*8;
                        float4 xr = make_float4(0.f, 0.f, 0.f, 0.f);
                        if (layer == 0) xr = *(const float4*)&xs_s[row * 4];
                        float hh[2];
#pragma unroll
                        for (int u = 0; u < 2; u++) {
                            float zi = acc[mi][0][rr*2+u], zf = acc[mi][1][rr*2+u];
                            float zg = acc[mi][2][rr*2+u], zo = acc[mi][3][rr*2+u];
                            if (layer == 0) {
                                zi += wq[0][u].x*xr.x + wq[0][u].y*xr.y + wq[0][u].z*xr.z + wq[0][u].w*xr.w;
                                zf += wq[1][u].x*xr.x + wq[1][u].y*xr.y + wq[1][u].z*xr.z + wq[1][u].w*xr.w;
                                zg += wq[2][u].x*xr.x + wq[2][u].y*xr.y + wq[2][u].z*xr.z + wq[2][u].w*xr.w;
                                zo += wq[3][u].x*xr.x + wq[3][u].y*xr.y + wq[3][u].z*xr.z + wq[3][u].w*xr.w;
                            }
                            int cidx = (mi*2+rr)*8 + ci*2 + u;
                            float cn = sigf(zf) * c_reg[cidx] + sigf(zi) * tanhf_(zg);
                            hh[u] = sigf(zo) * tanhf_(cn);
                            c_reg[cidx] = cn;
                        }
                        __nv_bfloat16 q0 = __float2bfloat16_rn(hh[0]), q1 = __float2bfloat16_rn(hh[1]);
                        u32 hw = (u32)*(unsigned short*)&q0 | ((u32)*(unsigned short*)&q1 << 16);
                        u32 lw = packbf(hh[0] - __bfloat162float(q0), hh[1] - __bfloat162float(q1));
                        int bo = row * 256 + ((2 * j0c) ^ ((row & 7) << 4));
                        if (layer == 0) {
                            char* bb = g_blob + ((size_t)blockIdx.x * Tv + ta) * 65536;
                            *(u32*)(bb + bo) = hw;
                            *(u32*)(bb + 32768 + bo) = lw;
                        } else {
                            char* bb = g_hb2 + ((size_t)(blockIdx.x * 2 + (t & 1))) * 65536;
                            *(u32*)(bb + bo) = hw;
                            *(u32*)(bb + 32768 + bo) = lw;
                            *(float2*)(g_r2 + (size_t)t * SLAB + (size_t)(bB + row) * 128 + j0c) =
                                make_float2(hh[0], hh[1]);
                        }
                    }
                }
                __syncthreads();
                if (s + 2 < 16) {
                    cp_slab(sb + B_OFF + ((u32)(s & 1) << 15), wbase + ((size_t)(s + 2) << 15), tid);
                    CP_COMMIT();
                }
            }
        }
    }
}

// ---- out = r2 @ Wcomb^T + bcomb ----
__global__ void out_kernel(const float* __restrict__ r2, float* __restrict__ out)
{
    __shared__ float sw[NYv * 129];
    __shared__ float sr[32][129];
    int tid = threadIdx.x;
    for (int i = tid; i < NYv * Hv; i += 128) {
        int y = i >> 7, k = i & 127;
        sw[y * 129 + k] = g_wcomb[i];
    }
    size_t base = (size_t)blockIdx.x * 32 * Hv;
    for (int i = tid; i < 32 * Hv; i += 128) {
        int rr = i >> 7, kk = i & 127;
        sr[rr][kk] = r2[base + i];
    }
    __syncthreads();
    int r = tid >> 2, y = tid & 3;
    int n = blockIdx.x * 32 + r;
    int t = n >> 14;
    int b = n & (Bv - 1);
    float acc = g_bcomb[y];
#pragma unroll 4
    for (int k = 0; k < Hv; k++) acc += sw[y * 129 + k] * sr[r][k];
    out[((size_t)b * Tv + t) * NYv + y] = acc;
}

__global__ void sfc_kernel(const float* __restrict__ Wsfc, const float* __restrict__ bsfc,
                           const float* __restrict__ hN, float* __restrict__ osfc)
{
    int i = blockIdx.x * blockDim.x + threadIdx.x;
    if (i >= Bv * NYSv) return;
    int b = i / 3, y = i - b * 3;
    const float* h = hN + (size_t)b * Hv;
    float acc = bsfc[y];
#pragma unroll 4
    for (int k = 0; k < Hv; k++) acc += Wsfc[y * Hv + k] * h[k];
    osfc[i] = acc;
}

// ---- launch ----
extern "C" void kernel_launch(void* const* d_in, const int* in_sizes, int n_in,
                              void* d_out, int out_size)
{
    const float* inputs_main = (const float*)d_in[0];
    const float* inputs_sfc  = (const float*)d_in[1];
    const float* mem0        = (const float*)d_in[2];
    const float* hx2         = (const float*)d_in[3];
    const float* cx2         = (const float*)d_in[4];
    const float* Ws1  = (const float*)d_in[5];
    const float* bs1  = (const float*)d_in[6];
    const float* Ws2  = (const float*)d_in[7];
    const float* bs2  = (const float*)d_in[8];
    const float* Wih1 = (const float*)d_in[9];
    const float* Whh1 = (const float*)d_in[10];
    const float* bih1 = (const float*)d_in[11];
    const float* bhh1 = (const float*)d_in[12];
    const float* Wih2 = (const float*)d_in[13];
    const float* Whh2 = (const float*)d_in[14];
    const float* bih2 = (const float*)d_in[15];
    const float* bhh2 = (const float*)d_in[16];
    const float* Wlat = (const float*)d_in[17];
    const float* blat = (const float*)d_in[18];
    const float* Wout = (const float*)d_in[19];
    const float* bout = (const float*)d_in[20];
    const float* Wsfc = (const float*)d_in[21];
    const float* bsfc = (const float*)d_in[22];
    float* out = (float*)d_out;

    float* r2;
    cudaGetSymbolAddress((void**)&r2, g_r2);

    init_kernel<<<(Bv * Hv + 255) / 256, 256>>>(inputs_sfc, Ws1, bs1, Ws2, bs2);

    const size_t CONV_N = (size_t)128 * Tv * 128 * 64;
    conv_mem0<<<(int)((CONV_N + 255) / 256), 256>>>(mem0);

    const int PREP_N = 2*16*2*128*64 + 2048 + 1024 + 512;
    prep_kernel<<<(PREP_N + 255) / 256, 256>>>(Wih1, Whh1, bih1, bhh1,
                                               Wih2, Whh2, bih2, bhh2,
                                               Wlat, blat, Wout, bout);

    cudaFuncSetAttribute(rnn_mma, cudaFuncAttributeMaxDynamicSharedMemorySize, SMEM_SZ);
    rnn_mma<<<128, 256, SMEM_SZ>>>(inputs_main, hx2, cx2);

    out_kernel<<<(Bv * Tv) / 32, 128>>>(r2, out);
    sfc_kernel<<<(Bv * NYSv + 255) / 256, 256>>>(Wsfc, bsfc,
                                                 r2 + (size_t)(Tv - 1) * Bv * Hv,
                                                 out + (size_t)Bv * Tv * NYv);
}